// round 6
// baseline (speedup 1.0000x reference)
#include <cuda_runtime.h>
#include <math.h>

#define D   256
#define NQ  512
#define NK  512

// ---------------- scratch ----------------
__device__ __align__(16) float g_aq[D * NQ];      // (d, n)
__device__ __align__(16) float g_ak[D * NK];      // (d, m)
__device__ __align__(16) float g_probT[NK * NQ];  // (m, n)
__device__ __align__(16) float g_msg[D * NQ];     // (d, n)
__device__ __align__(16) float g_h2[2 * D * NQ];  // (o, n)

// ---------------- 4-way split-K SGEMM core: tile BM x 64, 512 threads ------
// Four warpgroups (128 thr) each accumulate over K/4; partials reduced via a
// two-bank smem tree. Thread tile TO=BM/8 o x 4 n. KC=16.
// Row strides 512. DUAL: X rows <256 from X0, >=256 from X1.
template<int BM, bool DUAL>
__device__ __forceinline__ void gemm_core(
    const float* __restrict__ W, const float* __restrict__ X0,
    const float* __restrict__ X1, const float* __restrict__ bias,
    float* __restrict__ out, int K, bool relu)
{
    constexpr int TO = BM / 8;
    constexpr int WS = BM + 4;
    const int n0  = blockIdx.x * 64;
    const int o0  = blockIdx.y * BM;
    const int tid = threadIdx.x;
    const int wg  = tid >> 7;            // 0..3
    const int t   = tid & 127;

    const int nI  = t & 15;
    const int oG  = t >> 4;

    __shared__ __align__(16) float sW[4][16 * WS];
    __shared__ __align__(16) float sX[4][16 * 68];
    __shared__ __align__(16) float sR[2][128 * TO * 4];

    // W loader: BM=32 -> all 128 thr (1 f4); BM=16 -> t<64
    const int wo  = t >> 2;              // o row
    const int wf  = t & 3;               // f4 within 16 k
    const bool wAct = (BM == 32) || (t < 64);
    // X loader: 2 f4 per thread
    const int xn4 = t & 15;
    const int xkr = t >> 4;              // 0..7 -> rows xkr, xkr+8

    const int kb  = wg * (K >> 2);
    const int NIT = K >> 6;              // (K/4)/16

    float4 rw, rx[2];
    float4 acc[TO];
    #pragma unroll
    for (int j = 0; j < TO; j++) acc[j] = make_float4(0.f, 0.f, 0.f, 0.f);

    // prefetch tile 0
    {
        const int k0 = kb;
        if (wAct) rw = *(const float4*)&W[(o0 + wo) * 512 + k0 + wf * 4];
        const float* Xb = (!DUAL || k0 < 256) ? X0 + k0 * 512
                                              : X1 + (k0 - 256) * 512;
        #pragma unroll
        for (int p = 0; p < 2; p++)
            rx[p] = *(const float4*)&Xb[(xkr + p * 8) * 512 + n0 + xn4 * 4];
    }

    for (int it = 0; it < NIT; it++) {
        __syncthreads();                 // prior compute done reading smem
        if (wAct) {
            sW[wg][(wf * 4 + 0) * WS + wo] = rw.x;
            sW[wg][(wf * 4 + 1) * WS + wo] = rw.y;
            sW[wg][(wf * 4 + 2) * WS + wo] = rw.z;
            sW[wg][(wf * 4 + 3) * WS + wo] = rw.w;
        }
        #pragma unroll
        for (int p = 0; p < 2; p++)
            *(float4*)&sX[wg][(xkr + p * 8) * 68 + xn4 * 4] = rx[p];
        __syncthreads();

        if (it + 1 < NIT) {              // prefetch next (overlaps compute)
            const int k0 = kb + (it + 1) * 16;
            if (wAct) rw = *(const float4*)&W[(o0 + wo) * 512 + k0 + wf * 4];
            const float* Xb = (!DUAL || k0 < 256) ? X0 + k0 * 512
                                                  : X1 + (k0 - 256) * 512;
            #pragma unroll
            for (int p = 0; p < 2; p++)
                rx[p] = *(const float4*)&Xb[(xkr + p * 8) * 512 + n0 + xn4 * 4];
        }

        #pragma unroll
        for (int k = 0; k < 16; k++) {
            float4 xv = *(const float4*)&sX[wg][k * 68 + nI * 4];
            if (TO == 4) {
                float4 wv = *(const float4*)&sW[wg][k * WS + oG * 4];
                acc[0].x += wv.x * xv.x; acc[0].y += wv.x * xv.y;
                acc[0].z += wv.x * xv.z; acc[0].w += wv.x * xv.w;
                acc[1].x += wv.y * xv.x; acc[1].y += wv.y * xv.y;
                acc[1].z += wv.y * xv.z; acc[1].w += wv.y * xv.w;
                acc[2].x += wv.z * xv.x; acc[2].y += wv.z * xv.y;
                acc[2].z += wv.z * xv.z; acc[2].w += wv.z * xv.w;
                acc[3].x += wv.w * xv.x; acc[3].y += wv.w * xv.y;
                acc[3].z += wv.w * xv.z; acc[3].w += wv.w * xv.w;
            } else {
                float2 wv = *(const float2*)&sW[wg][k * WS + oG * 2];
                acc[0].x += wv.x * xv.x; acc[0].y += wv.x * xv.y;
                acc[0].z += wv.x * xv.z; acc[0].w += wv.x * xv.w;
                acc[1].x += wv.y * xv.x; acc[1].y += wv.y * xv.y;
                acc[1].z += wv.y * xv.z; acc[1].w += wv.y * xv.w;
            }
        }
    }

    // reduction tree: wg1->bank0, wg3->bank1 ; wg0+=b0, wg2+=b1 ; wg2->b0 ; wg0+=b0
    if (wg == 1) {
        #pragma unroll
        for (int j = 0; j < TO; j++) *(float4*)&sR[0][(t * TO + j) * 4] = acc[j];
    } else if (wg == 3) {
        #pragma unroll
        for (int j = 0; j < TO; j++) *(float4*)&sR[1][(t * TO + j) * 4] = acc[j];
    }
    __syncthreads();
    if (wg == 0) {
        #pragma unroll
        for (int j = 0; j < TO; j++) {
            float4 r = *(const float4*)&sR[0][(t * TO + j) * 4];
            acc[j].x += r.x; acc[j].y += r.y; acc[j].z += r.z; acc[j].w += r.w;
        }
    } else if (wg == 2) {
        #pragma unroll
        for (int j = 0; j < TO; j++) {
            float4 r = *(const float4*)&sR[1][(t * TO + j) * 4];
            acc[j].x += r.x; acc[j].y += r.y; acc[j].z += r.z; acc[j].w += r.w;
        }
    }
    __syncthreads();
    if (wg == 2) {
        #pragma unroll
        for (int j = 0; j < TO; j++) *(float4*)&sR[0][(t * TO + j) * 4] = acc[j];
    }
    __syncthreads();
    if (wg == 0) {
        #pragma unroll
        for (int j = 0; j < TO; j++) {
            float4 r = *(const float4*)&sR[0][(t * TO + j) * 4];
            const int o = o0 + oG * TO + j;
            const float b = bias ? bias[o] : 0.f;
            float4 v = acc[j];
            v.x += r.x + b; v.y += r.y + b; v.z += r.z + b; v.w += r.w + b;
            if (relu) {
                v.x = fmaxf(v.x, 0.f); v.y = fmaxf(v.y, 0.f);
                v.z = fmaxf(v.z, 0.f); v.w = fmaxf(v.w, 0.f);
            }
            *(float4*)&out[o * 512 + n0 + nI * 4] = v;
        }
    }
}

// ---------------- stage kernels ----------------

// aq = w1[:, :D] @ x + b1 ; ak = w1[:, D:] @ src     grid (8, 8, 2), 512 thr
__global__ void __launch_bounds__(512) k_qk(
    const float* __restrict__ w1, const float* __restrict__ x,
    const float* __restrict__ src, const float* __restrict__ b1)
{
    if (blockIdx.z == 0)
        gemm_core<32, false>(w1,       x,   nullptr, b1,      g_aq, 256, false);
    else
        gemm_core<32, false>(w1 + 256, src, nullptr, nullptr, g_ak, 256, false);
}

// scores[n][m] = sum_d w2[d]*relu(aq[d][n]+ak[d][m]) + b2    grid (8,16), 512 thr
// block tile 32 n x 64 m; 4 warpgroups split d (64 each); thread 4n x 4m
__global__ void __launch_bounds__(512) k_score(
    const float* __restrict__ w2, const float* __restrict__ b2,
    float* __restrict__ scores)
{
    const int m0  = blockIdx.x * 64;
    const int n0  = blockIdx.y * 32;
    const int tid = threadIdx.x;
    const int wg  = tid >> 7;
    const int t   = tid & 127;
    const int mI  = t & 15;
    const int nG  = t >> 4;

    __shared__ __align__(16) float sA[4][16 * 36];
    __shared__ __align__(16) float sB[4][16 * 68];
    __shared__ float sw[4][16];
    __shared__ __align__(16) float sR[2][128 * 16];

    const int adr = t >> 3, an4 = t & 7;    // A: 1 f4/thread
    const int bdr = t >> 4, bm4 = t & 15;   // B: 2 f4/thread
    const int db  = wg * 64;

    float4 ra, rb[2];
    float rwv;
    float4 acc[4];
    #pragma unroll
    for (int j = 0; j < 4; j++) acc[j] = make_float4(0.f, 0.f, 0.f, 0.f);

    // prefetch tile 0
    ra = *(const float4*)&g_aq[(db + adr) * 512 + n0 + an4 * 4];
    #pragma unroll
    for (int p = 0; p < 2; p++)
        rb[p] = *(const float4*)&g_ak[(db + bdr + p * 8) * 512 + m0 + bm4 * 4];
    rwv = (t < 16) ? w2[db + t] : 0.f;

    for (int it = 0; it < 4; it++) {
        __syncthreads();
        *(float4*)&sA[wg][adr * 36 + an4 * 4] = ra;
        #pragma unroll
        for (int p = 0; p < 2; p++)
            *(float4*)&sB[wg][(bdr + p * 8) * 68 + bm4 * 4] = rb[p];
        if (t < 16) sw[wg][t] = rwv;
        __syncthreads();

        if (it + 1 < 4) {
            const int d0 = db + (it + 1) * 16;
            ra = *(const float4*)&g_aq[(d0 + adr) * 512 + n0 + an4 * 4];
            #pragma unroll
            for (int p = 0; p < 2; p++)
                rb[p] = *(const float4*)&g_ak[(d0 + bdr + p * 8) * 512 + m0 + bm4 * 4];
            if (t < 16) rwv = w2[d0 + t];
        }

        #pragma unroll
        for (int d = 0; d < 16; d++) {
            float4 av = *(const float4*)&sA[wg][d * 36 + nG * 4];
            float4 bv = *(const float4*)&sB[wg][d * 68 + mI * 4];
            float w  = sw[wg][d];
            float a[4] = {av.x, av.y, av.z, av.w};
            #pragma unroll
            for (int j = 0; j < 4; j++) {
                acc[j].x += w * fmaxf(a[j] + bv.x, 0.f);
                acc[j].y += w * fmaxf(a[j] + bv.y, 0.f);
                acc[j].z += w * fmaxf(a[j] + bv.z, 0.f);
                acc[j].w += w * fmaxf(a[j] + bv.w, 0.f);
            }
        }
    }

    if (wg == 1) {
        #pragma unroll
        for (int j = 0; j < 4; j++) *(float4*)&sR[0][(t * 4 + j) * 4] = acc[j];
    } else if (wg == 3) {
        #pragma unroll
        for (int j = 0; j < 4; j++) *(float4*)&sR[1][(t * 4 + j) * 4] = acc[j];
    }
    __syncthreads();
    if (wg == 0) {
        #pragma unroll
        for (int j = 0; j < 4; j++) {
            float4 r = *(const float4*)&sR[0][(t * 4 + j) * 4];
            acc[j].x += r.x; acc[j].y += r.y; acc[j].z += r.z; acc[j].w += r.w;
        }
    } else if (wg == 2) {
        #pragma unroll
        for (int j = 0; j < 4; j++) {
            float4 r = *(const float4*)&sR[1][(t * 4 + j) * 4];
            acc[j].x += r.x; acc[j].y += r.y; acc[j].z += r.z; acc[j].w += r.w;
        }
    }
    __syncthreads();
    if (wg == 2) {
        #pragma unroll
        for (int j = 0; j < 4; j++) *(float4*)&sR[0][(t * 4 + j) * 4] = acc[j];
    }
    __syncthreads();
    if (wg == 0) {
        const float bs = b2[0];
        #pragma unroll
        for (int j = 0; j < 4; j++) {
            float4 r = *(const float4*)&sR[0][(t * 4 + j) * 4];
            const int n = n0 + nG * 4 + j;
            float4 v = acc[j];
            v.x += r.x + bs; v.y += r.y + bs;
            v.z += r.z + bs; v.w += r.w + bs;
            *(float4*)&scores[n * 512 + m0 + mI * 4] = v;
        }
    }
}

// softmax over m per row n, writing TRANSPOSED prob: g_probT[m][n]
__global__ void __launch_bounds__(128) k_softmaxT(const float* __restrict__ scores)
{
    const int n0   = blockIdx.x * 4;
    const int tid  = threadIdx.x;
    const int lane = tid & 31, w = tid >> 5;
    __shared__ float sP[4][513];

    const float* row = scores + (n0 + w) * 512;
    float v[16];
    float mx = -1e30f;
    #pragma unroll
    for (int i = 0; i < 16; i++) { v[i] = row[lane + 32 * i]; mx = fmaxf(mx, v[i]); }
    #pragma unroll
    for (int o = 16; o; o >>= 1) mx = fmaxf(mx, __shfl_xor_sync(0xffffffffu, mx, o));
    float s = 0.f;
    #pragma unroll
    for (int i = 0; i < 16; i++) { v[i] = __expf(v[i] - mx); s += v[i]; }
    #pragma unroll
    for (int o = 16; o; o >>= 1) s += __shfl_xor_sync(0xffffffffu, s, o);
    float inv = 1.f / s;
    #pragma unroll
    for (int i = 0; i < 16; i++) sP[w][lane + 32 * i] = v[i] * inv;
    __syncthreads();
    #pragma unroll
    for (int i = 0; i < 4; i++) {
        int m = tid + 128 * i;
        float4 t = make_float4(sP[0][m], sP[1][m], sP[2][m], sP[3][m]);
        *(float4*)&g_probT[m * 512 + n0] = t;
    }
}

// message[d][n] = sum_m src[d][m] * probT[m][n]      grid (8,16), 512 thr
__global__ void __launch_bounds__(512) k_msg(const float* __restrict__ src)
{
    gemm_core<16, false>(src, g_probT, nullptr, nullptr, g_msg, 512, false);
}

// h2 = relu(wa @ [x; msg] + ba)                      grid (8,16), 512 thr
__global__ void __launch_bounds__(512) k_h2(
    const float* __restrict__ wa, const float* __restrict__ x,
    const float* __restrict__ ba)
{
    gemm_core<32, true>(wa, x, g_msg, ba, g_h2, 512, true);
}

// y = wb @ h2 + bb                                   grid (8,16), 512 thr
__global__ void __launch_bounds__(512) k_y(
    const float* __restrict__ wb, const float* __restrict__ bb,
    float* __restrict__ y)
{
    gemm_core<16, false>(wb, g_h2, nullptr, bb, y, 512, false);
}

// ---------------- launch ----------------
extern "C" void kernel_launch(void* const* d_in, const int* in_sizes, int n_in,
                              void* d_out, int out_size)
{
    const float* x   = (const float*)d_in[0];
    const float* src = (const float*)d_in[1];
    const float* w1  = (const float*)d_in[2];
    const float* b1  = (const float*)d_in[3];
    const float* w2  = (const float*)d_in[4];
    const float* b2  = (const float*)d_in[5];
    const float* wa  = (const float*)d_in[6];
    const float* ba  = (const float*)d_in[7];
    const float* wb  = (const float*)d_in[8];
    const float* bb  = (const float*)d_in[9];

    float* y      = (float*)d_out;   // (1, D, NQ)
    float* scores = y + D * NQ;      // (1, NQ, NK)

    k_qk      <<<dim3(8, 8, 2), 512>>>(w1, x, src, b1);
    k_score   <<<dim3(8, 16),   512>>>(w2, b2, scores);
    k_softmaxT<<<128,           128>>>(scores);
    k_msg     <<<dim3(8, 16),   512>>>(src);
    k_h2      <<<dim3(8, 16),   512>>>(wa, x, ba);
    k_y       <<<dim3(8, 16),   512>>>(wb, bb, y);
}

// round 8
// speedup vs baseline: 1.0113x; 1.0113x over previous
#include <cuda_runtime.h>
#include <math.h>

#define D   256
#define NQ  512
#define NK  512

// ---------------- scratch ----------------
__device__ __align__(16) float g_aq[D * NQ];      // (d, n)
__device__ __align__(16) float g_ak[D * NK];      // (d, m)
__device__ __align__(16) float g_probT[NK * NQ];  // (m, n)
__device__ __align__(16) float g_msg[D * NQ];     // (d, n)
__device__ __align__(16) float g_h2[2 * D * NQ];  // (o, n)

// ============ 2-way split-K core (KC=32, 256 thr) — for K=256 ============
template<int BM, bool DUAL>
__device__ __forceinline__ void gemm2(
    const float* __restrict__ W, const float* __restrict__ X0,
    const float* __restrict__ X1, const float* __restrict__ bias,
    float* __restrict__ out, int K, bool relu)
{
    constexpr int TO = BM / 8;
    constexpr int WS = BM + 4;
    constexpr int NW = BM / 16;
    const int n0  = blockIdx.x * 64;
    const int o0  = blockIdx.y * BM;
    const int tid = threadIdx.x;
    const int wg  = tid >> 7;
    const int t   = tid & 127;
    const int nI  = t & 15;
    const int oG  = t >> 4;

    __shared__ __align__(16) float sW[2][32 * WS];
    __shared__ __align__(16) float sX[2][32 * 68];
    __shared__ __align__(16) float sR[128 * TO * 4];

    const int wo  = (BM == 32) ? (t >> 2) : (t >> 3);
    const int wf  = (BM == 32) ? (t & 3)  : (t & 7);
    const int xn4 = t & 15;
    const int xkr = t >> 4;

    const int kb  = wg * (K >> 1);
    const int NIT = K >> 6;

    float4 rw[NW], rx[4];
    float4 acc[TO];
    #pragma unroll
    for (int j = 0; j < TO; j++) acc[j] = make_float4(0.f, 0.f, 0.f, 0.f);

    {
        const int k0 = kb;
        #pragma unroll
        for (int p = 0; p < NW; p++)
            rw[p] = *(const float4*)&W[(o0 + wo) * 512 + k0 + (wf + p * 4) * 4];
        const float* Xb = (!DUAL || k0 < 256) ? X0 + k0 * 512
                                              : X1 + (k0 - 256) * 512;
        #pragma unroll
        for (int p = 0; p < 4; p++)
            rx[p] = *(const float4*)&Xb[(xkr + p * 8) * 512 + n0 + xn4 * 4];
    }

    for (int it = 0; it < NIT; it++) {
        __syncthreads();
        #pragma unroll
        for (int p = 0; p < NW; p++) {
            const int f4 = wf + p * 4;
            sW[wg][(f4 * 4 + 0) * WS + wo] = rw[p].x;
            sW[wg][(f4 * 4 + 1) * WS + wo] = rw[p].y;
            sW[wg][(f4 * 4 + 2) * WS + wo] = rw[p].z;
            sW[wg][(f4 * 4 + 3) * WS + wo] = rw[p].w;
        }
        #pragma unroll
        for (int p = 0; p < 4; p++)
            *(float4*)&sX[wg][(xkr + p * 8) * 68 + xn4 * 4] = rx[p];
        __syncthreads();

        if (it + 1 < NIT) {
            const int k0 = kb + (it + 1) * 32;
            #pragma unroll
            for (int p = 0; p < NW; p++)
                rw[p] = *(const float4*)&W[(o0 + wo) * 512 + k0 + (wf + p * 4) * 4];
            const float* Xb = (!DUAL || k0 < 256) ? X0 + k0 * 512
                                                  : X1 + (k0 - 256) * 512;
            #pragma unroll
            for (int p = 0; p < 4; p++)
                rx[p] = *(const float4*)&Xb[(xkr + p * 8) * 512 + n0 + xn4 * 4];
        }

        #pragma unroll
        for (int k = 0; k < 32; k++) {
            float4 xv = *(const float4*)&sX[wg][k * 68 + nI * 4];
            if (TO == 4) {
                float4 wv = *(const float4*)&sW[wg][k * WS + oG * 4];
                acc[0].x += wv.x * xv.x; acc[0].y += wv.x * xv.y;
                acc[0].z += wv.x * xv.z; acc[0].w += wv.x * xv.w;
                acc[1].x += wv.y * xv.x; acc[1].y += wv.y * xv.y;
                acc[1].z += wv.y * xv.z; acc[1].w += wv.y * xv.w;
                acc[2].x += wv.z * xv.x; acc[2].y += wv.z * xv.y;
                acc[2].z += wv.z * xv.z; acc[2].w += wv.z * xv.w;
                acc[3].x += wv.w * xv.x; acc[3].y += wv.w * xv.y;
                acc[3].z += wv.w * xv.z; acc[3].w += wv.w * xv.w;
            } else {
                float2 wv = *(const float2*)&sW[wg][k * WS + oG * 2];
                acc[0].x += wv.x * xv.x; acc[0].y += wv.x * xv.y;
                acc[0].z += wv.x * xv.z; acc[0].w += wv.x * xv.w;
                acc[1].x += wv.y * xv.x; acc[1].y += wv.y * xv.y;
                acc[1].z += wv.y * xv.z; acc[1].w += wv.y * xv.w;
            }
        }
    }

    if (wg == 1) {
        #pragma unroll
        for (int j = 0; j < TO; j++)
            *(float4*)&sR[(t * TO + j) * 4] = acc[j];
    }
    __syncthreads();
    if (wg == 0) {
        #pragma unroll
        for (int j = 0; j < TO; j++) {
            float4 r = *(const float4*)&sR[(t * TO + j) * 4];
            const int o = o0 + oG * TO + j;
            const float b = bias ? bias[o] : 0.f;
            float4 v = acc[j];
            v.x += r.x + b; v.y += r.y + b; v.z += r.z + b; v.w += r.w + b;
            if (relu) {
                v.x = fmaxf(v.x, 0.f); v.y = fmaxf(v.y, 0.f);
                v.z = fmaxf(v.z, 0.f); v.w = fmaxf(v.w, 0.f);
            }
            *(float4*)&out[o * 512 + n0 + nI * 4] = v;
        }
    }
}

// ============ 4-way split-K core (KC=16, 512 thr) — for K=512 ============
// syncDep: this thread must cudaGridDependencySynchronize before reading X.
template<int BM, bool DUAL>
__device__ __forceinline__ void gemm4(
    const float* __restrict__ W, const float* __restrict__ X0,
    const float* __restrict__ X1, const float* __restrict__ bias,
    float* __restrict__ out, int K, bool relu, bool syncDep)
{
    constexpr int TO = BM / 8;
    constexpr int WS = BM + 4;
    const int n0  = blockIdx.x * 64;
    const int o0  = blockIdx.y * BM;
    const int tid = threadIdx.x;
    const int wg  = tid >> 7;
    const int t   = tid & 127;
    const int nI  = t & 15;
    const int oG  = t >> 4;

    __shared__ __align__(16) float sW[4][16 * WS];
    __shared__ __align__(16) float sX[4][16 * 68];
    __shared__ __align__(16) float sR[2][128 * TO * 4];

    const int wo  = t >> 2;
    const int wf  = t & 3;
    const bool wAct = (BM == 32) || (t < 64);
    const int xn4 = t & 15;
    const int xkr = t >> 4;

    const int kb  = wg * (K >> 2);
    const int NIT = K >> 6;

    float4 rw, rx[2];
    float4 acc[TO];
    #pragma unroll
    for (int j = 0; j < TO; j++) acc[j] = make_float4(0.f, 0.f, 0.f, 0.f);

    // W is always a true input tensor: prefetch BEFORE the dependency sync.
    if (wAct) rw = *(const float4*)&W[(o0 + wo) * 512 + kb + wf * 4];
    if (syncDep) cudaGridDependencySynchronize();
    {
        const float* Xb = (!DUAL || kb < 256) ? X0 + kb * 512
                                              : X1 + (kb - 256) * 512;
        #pragma unroll
        for (int p = 0; p < 2; p++)
            rx[p] = *(const float4*)&Xb[(xkr + p * 8) * 512 + n0 + xn4 * 4];
    }

    for (int it = 0; it < NIT; it++) {
        __syncthreads();
        if (wAct) {
            sW[wg][(wf * 4 + 0) * WS + wo] = rw.x;
            sW[wg][(wf * 4 + 1) * WS + wo] = rw.y;
            sW[wg][(wf * 4 + 2) * WS + wo] = rw.z;
            sW[wg][(wf * 4 + 3) * WS + wo] = rw.w;
        }
        #pragma unroll
        for (int p = 0; p < 2; p++)
            *(float4*)&sX[wg][(xkr + p * 8) * 68 + xn4 * 4] = rx[p];
        __syncthreads();

        if (it + 1 < NIT) {
            const int k0 = kb + (it + 1) * 16;
            if (wAct) rw = *(const float4*)&W[(o0 + wo) * 512 + k0 + wf * 4];
            const float* Xb = (!DUAL || k0 < 256) ? X0 + k0 * 512
                                                  : X1 + (k0 - 256) * 512;
            #pragma unroll
            for (int p = 0; p < 2; p++)
                rx[p] = *(const float4*)&Xb[(xkr + p * 8) * 512 + n0 + xn4 * 4];
        }

        #pragma unroll
        for (int k = 0; k < 16; k++) {
            float4 xv = *(const float4*)&sX[wg][k * 68 + nI * 4];
            if (TO == 4) {
                float4 wv = *(const float4*)&sW[wg][k * WS + oG * 4];
                acc[0].x += wv.x * xv.x; acc[0].y += wv.x * xv.y;
                acc[0].z += wv.x * xv.z; acc[0].w += wv.x * xv.w;
                acc[1].x += wv.y * xv.x; acc[1].y += wv.y * xv.y;
                acc[1].z += wv.y * xv.z; acc[1].w += wv.y * xv.w;
                acc[2].x += wv.z * xv.x; acc[2].y += wv.z * xv.y;
                acc[2].z += wv.z * xv.z; acc[2].w += wv.z * xv.w;
                acc[3].x += wv.w * xv.x; acc[3].y += wv.w * xv.y;
                acc[3].z += wv.w * xv.z; acc[3].w += wv.w * xv.w;
            } else {
                float2 wv = *(const float2*)&sW[wg][k * WS + oG * 2];
                acc[0].x += wv.x * xv.x; acc[0].y += wv.x * xv.y;
                acc[0].z += wv.x * xv.z; acc[0].w += wv.x * xv.w;
                acc[1].x += wv.y * xv.x; acc[1].y += wv.y * xv.y;
                acc[1].z += wv.y * xv.z; acc[1].w += wv.y * xv.w;
            }
        }
    }

    if (wg == 1) {
        #pragma unroll
        for (int j = 0; j < TO; j++) *(float4*)&sR[0][(t * TO + j) * 4] = acc[j];
    } else if (wg == 3) {
        #pragma unroll
        for (int j = 0; j < TO; j++) *(float4*)&sR[1][(t * TO + j) * 4] = acc[j];
    }
    __syncthreads();
    if (wg == 0) {
        #pragma unroll
        for (int j = 0; j < TO; j++) {
            float4 r = *(const float4*)&sR[0][(t * TO + j) * 4];
            acc[j].x += r.x; acc[j].y += r.y; acc[j].z += r.z; acc[j].w += r.w;
        }
    } else if (wg == 2) {
        #pragma unroll
        for (int j = 0; j < TO; j++) {
            float4 r = *(const float4*)&sR[1][(t * TO + j) * 4];
            acc[j].x += r.x; acc[j].y += r.y; acc[j].z += r.z; acc[j].w += r.w;
        }
    }
    __syncthreads();
    if (wg == 2) {
        #pragma unroll
        for (int j = 0; j < TO; j++) *(float4*)&sR[0][(t * TO + j) * 4] = acc[j];
    }
    __syncthreads();
    if (wg == 0) {
        #pragma unroll
        for (int j = 0; j < TO; j++) {
            float4 r = *(const float4*)&sR[0][(t * TO + j) * 4];
            const int o = o0 + oG * TO + j;
            const float b = bias ? bias[o] : 0.f;
            float4 v = acc[j];
            v.x += r.x + b; v.y += r.y + b; v.z += r.z + b; v.w += r.w + b;
            if (relu) {
                v.x = fmaxf(v.x, 0.f); v.y = fmaxf(v.y, 0.f);
                v.z = fmaxf(v.z, 0.f); v.w = fmaxf(v.w, 0.f);
            }
            *(float4*)&out[o * 512 + n0 + nI * 4] = v;
        }
    }
}

// ---------------- stage kernels ----------------

// aq = w1[:, :D] @ x + b1 ; ak = w1[:, D:] @ src   grid (8,8,2), 256 thr
__global__ void __launch_bounds__(256) k_qk(
    const float* __restrict__ w1, const float* __restrict__ x,
    const float* __restrict__ src, const float* __restrict__ b1)
{
    if (blockIdx.z == 0)
        gemm2<32, false>(w1,       x,   nullptr, b1,      g_aq, 256, false);
    else
        gemm2<32, false>(w1 + 256, src, nullptr, nullptr, g_ak, 256, false);
    cudaTriggerProgrammaticLaunchCompletion();
}

// scores[n][m] = sum_d w2[d]*relu(aq[d][n]+ak[d][m]) + b2   grid (8,16), 512 thr
__global__ void __launch_bounds__(512) k_score(
    const float* __restrict__ w2, const float* __restrict__ b2,
    float* __restrict__ scores)
{
    const int m0  = blockIdx.x * 64;
    const int n0  = blockIdx.y * 32;
    const int tid = threadIdx.x;
    const int wg  = tid >> 7;
    const int t   = tid & 127;
    const int mI  = t & 15;
    const int nG  = t >> 4;

    __shared__ __align__(16) float sA[4][16 * 36];
    __shared__ __align__(16) float sB[4][16 * 68];
    __shared__ float sw[4][16];
    __shared__ __align__(16) float sR[2][128 * 16];

    const int adr = t >> 3, an4 = t & 7;
    const int bdr = t >> 4, bm4 = t & 15;
    const int db  = wg * 64;

    float4 ra, rb[2];
    float rwv;
    float4 acc[4];
    #pragma unroll
    for (int j = 0; j < 4; j++) acc[j] = make_float4(0.f, 0.f, 0.f, 0.f);

    rwv = (t < 16) ? w2[db + t] : 0.f;            // input: before sync
    cudaGridDependencySynchronize();              // wait for k_qk outputs
    ra = *(const float4*)&g_aq[(db + adr) * 512 + n0 + an4 * 4];
    #pragma unroll
    for (int p = 0; p < 2; p++)
        rb[p] = *(const float4*)&g_ak[(db + bdr + p * 8) * 512 + m0 + bm4 * 4];

    for (int it = 0; it < 4; it++) {
        __syncthreads();
        *(float4*)&sA[wg][adr * 36 + an4 * 4] = ra;
        #pragma unroll
        for (int p = 0; p < 2; p++)
            *(float4*)&sB[wg][(bdr + p * 8) * 68 + bm4 * 4] = rb[p];
        if (t < 16) sw[wg][t] = rwv;
        __syncthreads();

        if (it + 1 < 4) {
            const int d0 = db + (it + 1) * 16;
            ra = *(const float4*)&g_aq[(d0 + adr) * 512 + n0 + an4 * 4];
            #pragma unroll
            for (int p = 0; p < 2; p++)
                rb[p] = *(const float4*)&g_ak[(d0 + bdr + p * 8) * 512 + m0 + bm4 * 4];
            if (t < 16) rwv = w2[d0 + t];
        }

        #pragma unroll
        for (int d = 0; d < 16; d++) {
            float4 av = *(const float4*)&sA[wg][d * 36 + nG * 4];
            float4 bv = *(const float4*)&sB[wg][d * 68 + mI * 4];
            float w  = sw[wg][d];
            float a[4] = {av.x, av.y, av.z, av.w};
            #pragma unroll
            for (int j = 0; j < 4; j++) {
                acc[j].x += w * fmaxf(a[j] + bv.x, 0.f);
                acc[j].y += w * fmaxf(a[j] + bv.y, 0.f);
                acc[j].z += w * fmaxf(a[j] + bv.z, 0.f);
                acc[j].w += w * fmaxf(a[j] + bv.w, 0.f);
            }
        }
    }

    if (wg == 1) {
        #pragma unroll
        for (int j = 0; j < 4; j++) *(float4*)&sR[0][(t * 4 + j) * 4] = acc[j];
    } else if (wg == 3) {
        #pragma unroll
        for (int j = 0; j < 4; j++) *(float4*)&sR[1][(t * 4 + j) * 4] = acc[j];
    }
    __syncthreads();
    if (wg == 0) {
        #pragma unroll
        for (int j = 0; j < 4; j++) {
            float4 r = *(const float4*)&sR[0][(t * 4 + j) * 4];
            acc[j].x += r.x; acc[j].y += r.y; acc[j].z += r.z; acc[j].w += r.w;
        }
    } else if (wg == 2) {
        #pragma unroll
        for (int j = 0; j < 4; j++) {
            float4 r = *(const float4*)&sR[1][(t * 4 + j) * 4];
            acc[j].x += r.x; acc[j].y += r.y; acc[j].z += r.z; acc[j].w += r.w;
        }
    }
    __syncthreads();
    if (wg == 2) {
        #pragma unroll
        for (int j = 0; j < 4; j++) *(float4*)&sR[0][(t * 4 + j) * 4] = acc[j];
    }
    __syncthreads();
    if (wg == 0) {
        const float bs = b2[0];
        #pragma unroll
        for (int j = 0; j < 4; j++) {
            float4 r = *(const float4*)&sR[0][(t * 4 + j) * 4];
            const int n = n0 + nG * 4 + j;
            float4 v = acc[j];
            v.x += r.x + bs; v.y += r.y + bs;
            v.z += r.z + bs; v.w += r.w + bs;
            *(float4*)&scores[n * 512 + m0 + mI * 4] = v;
        }
    }
    cudaTriggerProgrammaticLaunchCompletion();
}

// softmax over m per row n -> transposed prob g_probT[m][n]   grid 128 x 128
__global__ void __launch_bounds__(128) k_softmaxT(const float* __restrict__ scores)
{
    const int n0   = blockIdx.x * 4;
    const int tid  = threadIdx.x;
    const int lane = tid & 31, w = tid >> 5;
    __shared__ float sP[4][513];

    cudaGridDependencySynchronize();              // wait for k_score
    const float* row = scores + (n0 + w) * 512;
    float v[16];
    float mx = -1e30f;
    #pragma unroll
    for (int i = 0; i < 16; i++) { v[i] = row[lane + 32 * i]; mx = fmaxf(mx, v[i]); }
    #pragma unroll
    for (int o = 16; o; o >>= 1) mx = fmaxf(mx, __shfl_xor_sync(0xffffffffu, mx, o));
    float s = 0.f;
    #pragma unroll
    for (int i = 0; i < 16; i++) { v[i] = __expf(v[i] - mx); s += v[i]; }
    #pragma unroll
    for (int o = 16; o; o >>= 1) s += __shfl_xor_sync(0xffffffffu, s, o);
    float inv = 1.f / s;
    #pragma unroll
    for (int i = 0; i < 16; i++) sP[w][lane + 32 * i] = v[i] * inv;
    __syncthreads();
    #pragma unroll
    for (int i = 0; i < 4; i++) {
        int m = tid + 128 * i;
        float4 t = make_float4(sP[0][m], sP[1][m], sP[2][m], sP[3][m]);
        *(float4*)&g_probT[m * 512 + n0] = t;
    }
    cudaTriggerProgrammaticLaunchCompletion();
}

// message = src @ probT          grid (8,16), 512 thr
__global__ void __launch_bounds__(512) k_msg(const float* __restrict__ src)
{
    gemm4<16, false>(src, g_probT, nullptr, nullptr, g_msg, 512, false, true);
    cudaTriggerProgrammaticLaunchCompletion();
}

// h2 = relu(wa @ [x; msg] + ba)  grid (8,16), 512 thr
// warpgroups 0/1 read only x (a true input) -> no dependency sync: they start
// while k_msg is still draining.
__global__ void __launch_bounds__(512) k_h2(
    const float* __restrict__ wa, const float* __restrict__ x,
    const float* __restrict__ ba)
{
    const bool dep = (threadIdx.x >> 7) >= 2;     // wg 2,3 touch g_msg
    gemm4<32, true>(wa, x, g_msg, ba, g_h2, 512, true, dep);
    cudaTriggerProgrammaticLaunchCompletion();
}

// y = wb @ h2 + bb               grid (8,16), 512 thr
__global__ void __launch_bounds__(512) k_y(
    const float* __restrict__ wb, const float* __restrict__ bb,
    float* __restrict__ y)
{
    gemm4<16, false>(wb, g_h2, nullptr, bb, y, 512, false, true);
    cudaTriggerProgrammaticLaunchCompletion();
}

// ---------------- launch ----------------
template<typename... Args>
static void launch_pdl(void (*kern)(Args...), dim3 grid, dim3 block, Args... args)
{
    cudaLaunchConfig_t cfg = {};
    cfg.gridDim = grid;
    cfg.blockDim = block;
    cfg.dynamicSmemBytes = 0;
    cfg.stream = 0;
    cudaLaunchAttribute at[1];
    at[0].id = cudaLaunchAttributeProgrammaticStreamSerialization;
    at[0].val.programmaticStreamSerializationAllowed = 1;
    cfg.attrs = at;
    cfg.numAttrs = 1;
    cudaLaunchKernelEx(&cfg, kern, args...);
}

extern "C" void kernel_launch(void* const* d_in, const int* in_sizes, int n_in,
                              void* d_out, int out_size)
{
    const float* x   = (const float*)d_in[0];
    const float* src = (const float*)d_in[1];
    const float* w1  = (const float*)d_in[2];
    const float* b1  = (const float*)d_in[3];
    const float* w2  = (const float*)d_in[4];
    const float* b2  = (const float*)d_in[5];
    const float* wa  = (const float*)d_in[6];
    const float* ba  = (const float*)d_in[7];
    const float* wb  = (const float*)d_in[8];
    const float* bb  = (const float*)d_in[9];

    float* y      = (float*)d_out;   // (1, D, NQ)
    float* scores = y + D * NQ;      // (1, NQ, NK)

    k_qk<<<dim3(8, 8, 2), 256>>>(w1, x, src, b1);               // no PDL (first)
    launch_pdl(k_score,    dim3(8, 16), dim3(512), w2, b2, (float*)scores);
    launch_pdl(k_softmaxT, dim3(128),   dim3(128), (const float*)scores);
    launch_pdl(k_msg,      dim3(8, 16), dim3(512), src);
    launch_pdl(k_h2,       dim3(8, 16), dim3(512), wa, x, ba);
    launch_pdl(k_y,        dim3(8, 16), dim3(512), wb, bb, y);
}